// round 8
// baseline (speedup 1.0000x reference)
#include <cuda_runtime.h>

// SSIM loss, fused separable 11x11 Gaussian, B=16 C=3 H=512 W=512 fp32.
// v8: field-pair packed HORIZONTAL conv.
//   Line buffer stores u64 field pairs P[c]=(mu1[c],mu2[c]), Q[c]=(q[c],p[c]);
//   horizontal 11-tap becomes packed f32x2 fma (half the issue slots of the
//   scalar version). Vertical conv unchanged (column-packed f32x2, reg ring).
//   grid = (9 chunks, 48 planes) = 432 blocks = 144 SM x 3 CTAs, 128 thr,
//   4 cols/thread, 2 rows per __syncthreads (double-set buffers).
// Finalization folded into the last block (atomicInc wrap, replay-safe).

#define HH 512
#define WW 512
#define NTHREADS 128
#define NPIX 12582912.0
#define GX 9
#define GY 48
#define NBLOCKS (GX * GY)

typedef unsigned long long u64;

__device__ constexpr float KW[11] = {
    0.00102839f, 0.00759876f, 0.03600077f, 0.10936069f, 0.21300554f,
    0.26601172f,
    0.21300554f, 0.10936069f, 0.03600077f, 0.00759876f, 0.00102839f};

__device__ double g_partial[NBLOCKS];
__device__ unsigned g_count = 0;

// ---- f32x2 packed helpers (sm_100+ PTX) ----
__device__ __forceinline__ u64 pk2(float lo, float hi) {
    u64 r; asm("mov.b64 %0, {%1, %2};" : "=l"(r) : "f"(lo), "f"(hi)); return r;
}
__device__ __forceinline__ void upk2(u64 v, float& lo, float& hi) {
    asm("mov.b64 {%0, %1}, %2;" : "=f"(lo), "=f"(hi) : "l"(v));
}
__device__ __forceinline__ u64 f2add(u64 a, u64 b) {
    u64 r; asm("add.rn.f32x2 %0, %1, %2;" : "=l"(r) : "l"(a), "l"(b)); return r;
}
__device__ __forceinline__ u64 f2mul(u64 a, u64 b) {
    u64 r; asm("mul.rn.f32x2 %0, %1, %2;" : "=l"(r) : "l"(a), "l"(b)); return r;
}
__device__ __forceinline__ u64 f2fma(u64 a, u64 b, u64 c) {
    u64 r; asm("fma.rn.f32x2 %0, %1, %2, %3;" : "=l"(r) : "l"(a), "l"(b), "l"(c));
    return r;
}

__device__ __forceinline__ void load_row_pk(const float* __restrict__ p,
                                            int row, int c0, u64 o[2]) {
    if ((unsigned)row < (unsigned)HH) {
        ulonglong2 v = *reinterpret_cast<const ulonglong2*>(p + row * WW + c0);
        o[0] = v.x;
        o[1] = v.y;
    } else {
        o[0] = 0ull; o[1] = 0ull;
    }
}

__global__ __launch_bounds__(NTHREADS, 3)
void ssim_kernel(const float* __restrict__ sr, const float* __restrict__ hr,
                 float* __restrict__ out) {
    const int plane = blockIdx.y;
    const int bx = blockIdx.x;
    // chunks: 58,58,58,58,56,56,56,56,56 (all even; sum = 512)
    const int r0 = (bx < 4) ? 58 * bx : (232 + 56 * (bx - 4));
    const int npairs = (bx < 4) ? 29 : 28;
    const int tid = threadIdx.x;
    const int c0 = tid * 4;

    const float* __restrict__ pa = sr + (size_t)plane * HH * WW;
    const float* __restrict__ pb = hr + (size_t)plane * HH * WW;

    // Line buffers: [set][row A/B][pairbuf P/Q][idx] u64; data col c at idx
    // c+8; halo zeros at idx [0..7] and [520..527].
    // P[c] = (mu1[c], mu2[c]); Q[c] = (q[c], p[c]).
    __shared__ __align__(16) u64 vsbuf[2][2][2][528];

    // halo init: 2 sets * 2 rows * 2 bufs * 16 halo u64 = 128 entries
    {
        int g = tid >> 4;              // 0..7
        int k = tid & 15;
        int idx = (k < 8) ? k : (512 + k);
        vsbuf[g >> 2][(g >> 1) & 1][g & 1][idx] = 0ull;
    }
    __syncthreads();

    // Packed weight constants (symmetric kernel -> 6 uniques).
    u64 WKP[6];
#pragma unroll
    for (int k = 0; k < 6; ++k) WKP[k] = pk2(KW[k], KW[k]);

    // Register ring of packed raw rows (last 11 loaded rows).
    u64 ra[11][2], rb[11][2], na[2], nb[2];
#pragma unroll
    for (int k = 0; k < 10; ++k) {
        load_row_pk(pa, r0 - 5 + k, c0, ra[k + 1]);
        load_row_pk(pb, r0 - 5 + k, c0, rb[k + 1]);
    }
    load_row_pk(pa, r0 + 5, c0, na);
    load_row_pk(pb, r0 + 5, c0, nb);

    float acc = 0.f;

#pragma unroll 2
    for (int p = 0; p < npairs; ++p) {
        const int set = p & 1;
        const int i = 2 * p;

        // ---------- vertical conv for rows A (r=0) and B (r=1) ----------
#pragma unroll
        for (int r = 0; r < 2; ++r) {
            // shift ring, consume prefetch, prefetch next row
#pragma unroll
            for (int k = 0; k < 10; ++k) {
#pragma unroll
                for (int q = 0; q < 2; ++q) {
                    ra[k][q] = ra[k + 1][q];
                    rb[k][q] = rb[k + 1][q];
                }
            }
#pragma unroll
            for (int q = 0; q < 2; ++q) { ra[10][q] = na[q]; rb[10][q] = nb[q]; }
            load_row_pk(pa, r0 + 6 + i + r, c0, na);
            load_row_pk(pb, r0 + 6 + i + r, c0, nb);

            u64 s0[2], s1[2], sqa[2], sqb[2], srr[2];
#pragma unroll
            for (int q = 0; q < 2; ++q) {
                u64 a = ra[5][q], b = rb[5][q];
                u64 wa = f2mul(WKP[5], a);
                u64 wb = f2mul(WKP[5], b);
                s0[q] = wa; s1[q] = wb;
                sqa[q] = f2mul(wa, a);
                sqb[q] = f2mul(wb, b);
                srr[q] = f2mul(wa, b);
            }
#pragma unroll
            for (int k = 0; k < 11; ++k) {
                if (k == 5) continue;
                const int wi = (k < 5) ? k : (10 - k);
#pragma unroll
                for (int q = 0; q < 2; ++q) {
                    u64 a = ra[k][q], b = rb[k][q];
                    u64 wa = f2mul(WKP[wi], a);
                    u64 wb = f2mul(WKP[wi], b);
                    s0[q]  = f2add(s0[q], wa);
                    s1[q]  = f2add(s1[q], wb);
                    sqa[q] = f2fma(wa, a, sqa[q]);
                    sqb[q] = f2fma(wb, b, sqb[q]);
                    srr[q] = f2fma(wa, b, srr[q]);
                }
            }

            // transpose to field pairs and publish (2 STS.128 per buf)
#pragma unroll
            for (int q = 0; q < 2; ++q) {
                u64 qs = f2add(sqa[q], sqb[q]);
                float a0, a1, b0, b1, q0, q1, p0, p1;
                upk2(s0[q], a0, a1);
                upk2(s1[q], b0, b1);
                upk2(qs, q0, q1);
                upk2(srr[q], p0, p1);
                ulonglong2 tP, tQ;
                tP.x = pk2(a0, b0); tP.y = pk2(a1, b1);
                tQ.x = pk2(q0, p0); tQ.y = pk2(q1, p1);
                *reinterpret_cast<ulonglong2*>(
                    &vsbuf[set][r][0][8 + c0 + 2 * q]) = tP;
                *reinterpret_cast<ulonglong2*>(
                    &vsbuf[set][r][1][8 + c0 + 2 * q]) = tQ;
            }
        }

        __syncthreads();  // the only barrier per 2 rows

        // ---------- horizontal conv + map for rows A and B ----------
#pragma unroll
        for (int r = 0; r < 2; ++r) {
            // load windows: u64 idx (8+c0-6+m) = c0+2+m, m=0..15, via
            // 8 aligned LDS.128 per pair-buf. Window used: m = 1..14.
            u64 WP[16], WQ[16];
            const ulonglong2* basP = reinterpret_cast<const ulonglong2*>(
                &vsbuf[set][r][0][c0 + 2]);
            const ulonglong2* basQ = reinterpret_cast<const ulonglong2*>(
                &vsbuf[set][r][1][c0 + 2]);
#pragma unroll
            for (int m = 0; m < 8; ++m) {
                ulonglong2 t = basP[m];
                WP[2 * m] = t.x; WP[2 * m + 1] = t.y;
            }
#pragma unroll
            for (int m = 0; m < 8; ++m) {
                ulonglong2 t = basQ[m];
                WQ[2 * m] = t.x; WQ[2 * m + 1] = t.y;
            }
#pragma unroll
            for (int j = 0; j < 4; ++j) {
                // packed horizontal conv: accP=(m1,m2), accQ=(q,p)
                u64 accP = f2mul(WKP[5], WP[6 + j]);
                u64 accQ = f2mul(WKP[5], WQ[6 + j]);
#pragma unroll
                for (int k = 0; k < 11; ++k) {
                    if (k == 5) continue;
                    const int wi = (k < 5) ? k : (10 - k);
                    accP = f2fma(WKP[wi], WP[1 + j + k], accP);
                    accQ = f2fma(WKP[wi], WQ[1 + j + k], accQ);
                }
                // scalar SSIM map for this column
                float m1, m2, qv, pv;
                upk2(accP, m1, m2);
                upk2(accQ, qv, pv);
                float m12 = m1 * m2;
                float sms = fmaf(m1, m1, m2 * m2);
                float num1 = fmaf(m12, 2.f, 1e-4f);
                float sig12 = pv - m12;
                float num2 = fmaf(sig12, 2.f, 9e-4f);
                float den1 = sms + 1e-4f;
                float den2 = (qv - sms) + 9e-4f;
                acc += __fdividef(num1 * num2, den1 * den2);
            }
        }
        // no trailing barrier: next pair writes the other set; reuse of this
        // set is fenced by the next __syncthreads.
    }

    // block reduction -> per-block partial
#pragma unroll
    for (int o = 16; o > 0; o >>= 1)
        acc += __shfl_down_sync(0xFFFFFFFFu, acc, o);

    __shared__ float wsum[4];
    __shared__ int is_last;
    if ((tid & 31) == 0) wsum[tid >> 5] = acc;
    __syncthreads();
    if (tid == 0) {
        double s = (double)wsum[0] + (double)wsum[1] + (double)wsum[2] +
                   (double)wsum[3];
        g_partial[blockIdx.y * GX + blockIdx.x] = s;
        __threadfence();
        unsigned old = atomicInc(&g_count, NBLOCKS - 1);  // wraps to 0
        is_last = (old == NBLOCKS - 1);
    }
    __syncthreads();

    // last block finalizes (replay-deterministic: counter wraps to 0)
    if (is_last) {
        __threadfence();
        double s = 0.0;
        for (int i2 = tid; i2 < NBLOCKS; i2 += NTHREADS)
            s += __ldcg(&g_partial[i2]);
#pragma unroll
        for (int o = 16; o > 0; o >>= 1)
            s += __shfl_down_sync(0xFFFFFFFFu, s, o);
        __shared__ double dsm[4];
        if ((tid & 31) == 0) dsm[tid >> 5] = s;
        __syncthreads();
        if (tid == 0) {
            double tot = dsm[0] + dsm[1] + dsm[2] + dsm[3];
            out[0] = (float)(1.0 - tot / NPIX);
        }
    }
}

extern "C" void kernel_launch(void* const* d_in, const int* in_sizes, int n_in,
                              void* d_out, int out_size) {
    const float* sr = (const float*)d_in[0];
    const float* hr = (const float*)d_in[1];
    float* out = (float*)d_out;

    dim3 grid(GX, GY);
    ssim_kernel<<<grid, NTHREADS>>>(sr, hr, out);
}